// round 11
// baseline (speedup 1.0000x reference)
#include <cuda_runtime.h>
#include <stdint.h>

#define D_IN   64
#define D_OUT  128
#define MAX_NODES 100000
#define MAX_EDGES 1600000

#define SCAN_CHUNK 4096           // 1024 threads * 4 elems
#define SCAN_LOG2  12
#define SCAN_BLOCKS ((MAX_NODES + 1 + SCAN_CHUNK - 1) / SCAN_CHUNK)   // 25

// Scratch (device globals; zero-initialized at module load; no allocs allowed)
__device__ int   g_cnt[MAX_NODES + 1];   // per-dst counts (zero at every entry)
__device__ int   g_off[MAX_NODES + 1];   // per-block exclusive offsets
__device__ int   g_rank[MAX_EDGES];      // within-bucket rank from histogram
__device__ int   g_esrc[MAX_EDGES];      // src ids sorted by dst bucket
__device__ int   g_bsum[SCAN_BLOCKS];    // exclusive block sums
__device__ float g_rst[MAX_NODES * D_IN];

// ---------------------------------------------------------------------------
// 1) histogram of dst; atomicAdd return value = within-bucket rank (free).
//    g_cnt is zero at entry: BSS on first call, fill re-zeroes for next call.
// ---------------------------------------------------------------------------
__global__ void hist_kernel(const int* __restrict__ dst, int e) {
    int i = blockIdx.x * blockDim.x + threadIdx.x;
    if (i < e) {
        g_rank[i] = atomicAdd(&g_cnt[dst[i]], 1);
    }
}

// ---------------------------------------------------------------------------
// 2a) per-block exclusive scan (1024 threads x 4 elems)
// ---------------------------------------------------------------------------
__global__ __launch_bounds__(1024)
void scan1_kernel(int nelem) {
    __shared__ int s[1024];
    int t = threadIdx.x;
    int base = blockIdx.x * SCAN_CHUNK + t * 4;

    int v0 = (base + 0 < nelem) ? g_cnt[base + 0] : 0;
    int v1 = (base + 1 < nelem) ? g_cnt[base + 1] : 0;
    int v2 = (base + 2 < nelem) ? g_cnt[base + 2] : 0;
    int v3 = (base + 3 < nelem) ? g_cnt[base + 3] : 0;
    int tsum = v0 + v1 + v2 + v3;

    s[t] = tsum;
    __syncthreads();
    #pragma unroll
    for (int off = 1; off < 1024; off <<= 1) {
        int x = (t >= off) ? s[t - off] : 0;
        __syncthreads();
        if (t >= off) s[t] += x;
        __syncthreads();
    }
    int excl = s[t] - tsum;
    if (t == 1023) g_bsum[blockIdx.x] = s[1023];

    int run = excl;
    if (base + 0 < nelem) { g_off[base + 0] = run; } run += v0;
    if (base + 1 < nelem) { g_off[base + 1] = run; } run += v1;
    if (base + 2 < nelem) { g_off[base + 2] = run; } run += v2;
    if (base + 3 < nelem) { g_off[base + 3] = run; }
}

// 2b) exclusive scan of block sums — single-warp shfl scan (nblocks<=32)
__global__ void scan2_kernel(int nblocks) {
    int lane = threadIdx.x;
    int v = (lane < nblocks) ? g_bsum[lane] : 0;
    int orig = v;
    #pragma unroll
    for (int off = 1; off < 32; off <<= 1) {
        int x = __shfl_up_sync(0xFFFFFFFFu, v, off);
        if (lane >= off) v += x;
    }
    if (lane < nblocks) g_bsum[lane] = v - orig;   // exclusive
}

// final offset of element i = g_off[i] + g_bsum[i >> SCAN_LOG2]
__device__ __forceinline__ int final_off(int i) {
    return __ldg(&g_off[i]) + __ldg(&g_bsum[i >> SCAN_LOG2]);
}

// ---------------------------------------------------------------------------
// 3) fill sorted src list (no atomics) + re-zero g_cnt for the next call
// ---------------------------------------------------------------------------
__global__ void fill_kernel(const int* __restrict__ src,
                            const int* __restrict__ dst, int e, int nelem) {
    int i = blockIdx.x * blockDim.x + threadIdx.x;
    if (i < e) {
        int d = dst[i];
        int p = final_off(d) + g_rank[i];
        g_esrc[p] = src[i];
    }
    if (i < nelem) g_cnt[i] = 0;
}

// ---------------------------------------------------------------------------
// 4) segment reduce: HALF-WARP (16 lanes x float4) per node, warp covers 2
//    nodes. 8-deep unroll: 8 broadcast index loads then 8 independent
//    LDG.128 gathers in flight. Two accumulator chains.
// ---------------------------------------------------------------------------
__global__ __launch_bounds__(256)
void accumulate_kernel(const float4* __restrict__ feat4, int n) {
    int gtid = blockIdx.x * blockDim.x + threadIdx.x;
    int node = gtid >> 4;          // 16 lanes per node
    int hl   = threadIdx.x & 15;   // float4 index within the 64-float row
    if (node >= n) return;

    float4 acc0 = __ldg(&feat4[(size_t)node * 16 + hl]);
    float4 acc1 = make_float4(0.f, 0.f, 0.f, 0.f);

    int j   = final_off(node);
    int end = final_off(node + 1);

    for (; j + 8 <= end; j += 8) {
        int s0 = __ldg(&g_esrc[j + 0]);
        int s1 = __ldg(&g_esrc[j + 1]);
        int s2 = __ldg(&g_esrc[j + 2]);
        int s3 = __ldg(&g_esrc[j + 3]);
        int s4 = __ldg(&g_esrc[j + 4]);
        int s5 = __ldg(&g_esrc[j + 5]);
        int s6 = __ldg(&g_esrc[j + 6]);
        int s7 = __ldg(&g_esrc[j + 7]);
        float4 v0 = __ldg(&feat4[(size_t)s0 * 16 + hl]);
        float4 v1 = __ldg(&feat4[(size_t)s1 * 16 + hl]);
        float4 v2 = __ldg(&feat4[(size_t)s2 * 16 + hl]);
        float4 v3 = __ldg(&feat4[(size_t)s3 * 16 + hl]);
        float4 v4 = __ldg(&feat4[(size_t)s4 * 16 + hl]);
        float4 v5 = __ldg(&feat4[(size_t)s5 * 16 + hl]);
        float4 v6 = __ldg(&feat4[(size_t)s6 * 16 + hl]);
        float4 v7 = __ldg(&feat4[(size_t)s7 * 16 + hl]);
        acc0.x += (v0.x + v1.x) + (v2.x + v3.x);
        acc0.y += (v0.y + v1.y) + (v2.y + v3.y);
        acc0.z += (v0.z + v1.z) + (v2.z + v3.z);
        acc0.w += (v0.w + v1.w) + (v2.w + v3.w);
        acc1.x += (v4.x + v5.x) + (v6.x + v7.x);
        acc1.y += (v4.y + v5.y) + (v6.y + v7.y);
        acc1.z += (v4.z + v5.z) + (v6.z + v7.z);
        acc1.w += (v4.w + v5.w) + (v6.w + v7.w);
    }
    for (; j + 2 <= end; j += 2) {
        int s0 = __ldg(&g_esrc[j + 0]);
        int s1 = __ldg(&g_esrc[j + 1]);
        float4 v0 = __ldg(&feat4[(size_t)s0 * 16 + hl]);
        float4 v1 = __ldg(&feat4[(size_t)s1 * 16 + hl]);
        acc0.x += v0.x; acc0.y += v0.y; acc0.z += v0.z; acc0.w += v0.w;
        acc1.x += v1.x; acc1.y += v1.y; acc1.z += v1.z; acc1.w += v1.w;
    }
    if (j < end) {
        int s = __ldg(&g_esrc[j]);
        float4 v = __ldg(&feat4[(size_t)s * 16 + hl]);
        acc0.x += v.x; acc0.y += v.y; acc0.z += v.z; acc0.w += v.w;
    }

    float4 outv = make_float4(acc0.x + acc1.x, acc0.y + acc1.y,
                              acc0.z + acc1.z, acc0.w + acc1.w);
    reinterpret_cast<float4*>(g_rst)[(size_t)node * 16 + hl] = outv;
}

// ---------------------------------------------------------------------------
// 5) out[n][o] = b[o] + sum_d rst[n][d] * W[o][d]
// ---------------------------------------------------------------------------
#define NODES_PER_BLOCK 16

__global__ __launch_bounds__(D_OUT, 4)
void gemm_out_kernel(const float* __restrict__ W,
                     const float* __restrict__ b,
                     float* __restrict__ out,
                     int n) {
    __shared__ float4 s_rst4[NODES_PER_BLOCK * (D_IN / 4)];

    int t = threadIdx.x;          // output column 0..127
    int node0 = blockIdx.x * NODES_PER_BLOCK;

    #pragma unroll
    for (int r = 0; r < 2; r++) {
        int idx = t + r * D_OUT;           // 0..255
        int node = node0 + (idx >> 4);
        float4 v = make_float4(0.f, 0.f, 0.f, 0.f);
        if (node < n) {
            v = reinterpret_cast<const float4*>(g_rst)[(size_t)node * 16 + (idx & 15)];
        }
        s_rst4[idx] = v;
    }
    __syncthreads();

    float4 w[D_IN / 4];
    const float4* Wrow4 = reinterpret_cast<const float4*>(W + (size_t)t * D_IN);
    #pragma unroll
    for (int k = 0; k < D_IN / 4; k++) {
        w[k] = __ldg(&Wrow4[k]);
    }
    float bias = __ldg(&b[t]);

    #pragma unroll
    for (int i = 0; i < NODES_PER_BLOCK; i++) {
        int node = node0 + i;
        if (node >= n) break;
        float acc = bias;
        const float4* r4 = &s_rst4[i * (D_IN / 4)];
        #pragma unroll
        for (int k = 0; k < D_IN / 4; k++) {
            float4 v = r4[k];
            acc += v.x * w[k].x + v.y * w[k].y + v.z * w[k].z + v.w * w[k].w;
        }
        out[(size_t)node * D_OUT + t] = acc;
    }
}

// ---------------------------------------------------------------------------
// Inputs: feat [N*64] f32, radius [E] f32 (dead: weight = ones_like),
//         src [E] i32, dst [E] i32, W [128*64] f32, b [128] f32.
// Output: [N*128] f32.
// ---------------------------------------------------------------------------
extern "C" void kernel_launch(void* const* d_in, const int* in_sizes, int n_in,
                              void* d_out, int out_size) {
    const float* feat = (const float*)d_in[0];
    const int*   src  = (const int*)d_in[2];
    const int*   dst  = (const int*)d_in[3];
    const float* W    = (const float*)d_in[4];
    const float* b    = (const float*)d_in[5];
    float* out = (float*)d_out;

    int n = in_sizes[0] / D_IN;   // 100000
    int e = in_sizes[2];          // 1600000
    int nelem = n + 1;

    // CSR build: hist -> scan1 -> scan2 -> fill (fill re-zeroes g_cnt)
    hist_kernel<<<(e + 255) / 256, 256>>>(dst, e);
    int nsb = (nelem + SCAN_CHUNK - 1) / SCAN_CHUNK;
    scan1_kernel<<<nsb, 1024>>>(nelem);
    scan2_kernel<<<1, 32>>>(nsb);
    fill_kernel<<<(e + 255) / 256, 256>>>(src, dst, e, nelem);

    // Segment reduce: half-warp per node (16 nodes per 256-thread block)
    {
        int blocks = (n * 16 + 255) / 256;
        accumulate_kernel<<<blocks, 256>>>(
            reinterpret_cast<const float4*>(feat), n);
    }

    // out = rst @ W^T + b
    gemm_out_kernel<<<(n + NODES_PER_BLOCK - 1) / NODES_PER_BLOCK, D_OUT>>>(
        W, b, out, n);
}

// round 12
// speedup vs baseline: 1.0233x; 1.0233x over previous
#include <cuda_runtime.h>
#include <stdint.h>

#define D_IN   64
#define D_OUT  128
#define MAX_NODES 100000
#define MAX_EDGES 1600000

#define SCAN_CHUNK 4096           // 1024 threads * 4 elems
#define SCAN_LOG2  12
#define SCAN_BLOCKS 32            // upper bound for smem scan (actual 25)

// Scratch (device globals; zero-initialized at module load; no allocs allowed)
__device__ int   g_cnt[MAX_NODES + 1];   // per-dst counts (zero at every entry)
__device__ int   g_off[MAX_NODES + 1];   // per-block exclusive offsets
__device__ int   g_rank[MAX_EDGES];      // within-bucket rank from histogram
__device__ int   g_esrc[MAX_EDGES];      // src ids sorted by dst bucket
__device__ int   g_bsum[SCAN_BLOCKS];    // RAW per-block aggregates
__device__ float g_rst[MAX_NODES * D_IN];

// ---------------------------------------------------------------------------
// 1) histogram of dst; atomicAdd return value = within-bucket rank (free).
//    g_cnt is zero at entry: BSS on first call, fill re-zeroes for next call.
// ---------------------------------------------------------------------------
__global__ void hist_kernel(const int* __restrict__ dst, int e) {
    int i = blockIdx.x * blockDim.x + threadIdx.x;
    if (i < e) {
        g_rank[i] = atomicAdd(&g_cnt[dst[i]], 1);
    }
}

// ---------------------------------------------------------------------------
// 2) per-block exclusive scan (1024 threads x 4 elems); writes per-block
//    offsets to g_off and RAW block aggregates to g_bsum.
// ---------------------------------------------------------------------------
__global__ __launch_bounds__(1024)
void scan1_kernel(int nelem) {
    __shared__ int s[1024];
    int t = threadIdx.x;
    int base = blockIdx.x * SCAN_CHUNK + t * 4;

    int v0 = (base + 0 < nelem) ? g_cnt[base + 0] : 0;
    int v1 = (base + 1 < nelem) ? g_cnt[base + 1] : 0;
    int v2 = (base + 2 < nelem) ? g_cnt[base + 2] : 0;
    int v3 = (base + 3 < nelem) ? g_cnt[base + 3] : 0;
    int tsum = v0 + v1 + v2 + v3;

    s[t] = tsum;
    __syncthreads();
    #pragma unroll
    for (int off = 1; off < 1024; off <<= 1) {
        int x = (t >= off) ? s[t - off] : 0;
        __syncthreads();
        if (t >= off) s[t] += x;
        __syncthreads();
    }
    int excl = s[t] - tsum;
    if (t == 1023) g_bsum[blockIdx.x] = s[1023];   // raw aggregate

    int run = excl;
    if (base + 0 < nelem) { g_off[base + 0] = run; } run += v0;
    if (base + 1 < nelem) { g_off[base + 1] = run; } run += v1;
    if (base + 2 < nelem) { g_off[base + 2] = run; } run += v2;
    if (base + 3 < nelem) { g_off[base + 3] = run; }
}

// Per-block smem preamble: exclusive scan of raw g_bsum aggregates (nsb<=32).
// Warp 0 only; all 32 lanes convergent; full mask -> legal. One barrier.
__device__ __forceinline__ void load_bsum_excl(int* s_bsumx, int nsb) {
    if (threadIdx.x < 32) {
        int lane = threadIdx.x;
        int v = (lane < nsb) ? __ldg(&g_bsum[lane]) : 0;
        int orig = v;
        #pragma unroll
        for (int off = 1; off < 32; off <<= 1) {
            int x = __shfl_up_sync(0xFFFFFFFFu, v, off);
            if (lane >= off) v += x;
        }
        if (lane < 32) s_bsumx[lane] = v - orig;
    }
    __syncthreads();
}

// ---------------------------------------------------------------------------
// 3) fill sorted src list (no atomics) + re-zero g_cnt for the next call
// ---------------------------------------------------------------------------
__global__ __launch_bounds__(256)
void fill_kernel(const int* __restrict__ src,
                 const int* __restrict__ dst, int e, int nelem, int nsb) {
    __shared__ int s_bsumx[SCAN_BLOCKS];
    load_bsum_excl(s_bsumx, nsb);

    int i = blockIdx.x * blockDim.x + threadIdx.x;
    if (i < e) {
        int d = dst[i];
        int p = __ldg(&g_off[d]) + s_bsumx[d >> SCAN_LOG2] + g_rank[i];
        g_esrc[p] = src[i];
    }
    if (i < nelem) g_cnt[i] = 0;
}

// ---------------------------------------------------------------------------
// 4) segment reduce: HALF-WARP (16 lanes x float4) per node, warp covers 2
//    nodes. 4-deep unroll, two accumulator chains (R8-measured version).
// ---------------------------------------------------------------------------
__global__ __launch_bounds__(256)
void accumulate_kernel(const float4* __restrict__ feat4, int n, int nsb) {
    __shared__ int s_bsumx[SCAN_BLOCKS];
    load_bsum_excl(s_bsumx, nsb);

    int gtid = blockIdx.x * blockDim.x + threadIdx.x;
    int node = gtid >> 4;          // 16 lanes per node
    int hl   = threadIdx.x & 15;   // float4 index within the 64-float row
    if (node >= n) return;

    float4 acc0 = __ldg(&feat4[(size_t)node * 16 + hl]);
    float4 acc1 = make_float4(0.f, 0.f, 0.f, 0.f);

    int j   = __ldg(&g_off[node])     + s_bsumx[node >> SCAN_LOG2];
    int end = __ldg(&g_off[node + 1]) + s_bsumx[(node + 1) >> SCAN_LOG2];

    for (; j + 4 <= end; j += 4) {
        int s0 = __ldg(&g_esrc[j + 0]);
        int s1 = __ldg(&g_esrc[j + 1]);
        int s2 = __ldg(&g_esrc[j + 2]);
        int s3 = __ldg(&g_esrc[j + 3]);
        float4 v0 = __ldg(&feat4[(size_t)s0 * 16 + hl]);
        float4 v1 = __ldg(&feat4[(size_t)s1 * 16 + hl]);
        float4 v2 = __ldg(&feat4[(size_t)s2 * 16 + hl]);
        float4 v3 = __ldg(&feat4[(size_t)s3 * 16 + hl]);
        acc0.x += v0.x + v1.x;  acc1.x += v2.x + v3.x;
        acc0.y += v0.y + v1.y;  acc1.y += v2.y + v3.y;
        acc0.z += v0.z + v1.z;  acc1.z += v2.z + v3.z;
        acc0.w += v0.w + v1.w;  acc1.w += v2.w + v3.w;
    }
    for (; j < end; j++) {
        int s = __ldg(&g_esrc[j]);
        float4 v = __ldg(&feat4[(size_t)s * 16 + hl]);
        acc0.x += v.x; acc0.y += v.y; acc0.z += v.z; acc0.w += v.w;
    }

    float4 outv = make_float4(acc0.x + acc1.x, acc0.y + acc1.y,
                              acc0.z + acc1.z, acc0.w + acc1.w);
    reinterpret_cast<float4*>(g_rst)[(size_t)node * 16 + hl] = outv;
}

// ---------------------------------------------------------------------------
// 5) out[n][o] = b[o] + sum_d rst[n][d] * W[o][d]
// ---------------------------------------------------------------------------
#define NODES_PER_BLOCK 16

__global__ __launch_bounds__(D_OUT, 4)
void gemm_out_kernel(const float* __restrict__ W,
                     const float* __restrict__ b,
                     float* __restrict__ out,
                     int n) {
    __shared__ float4 s_rst4[NODES_PER_BLOCK * (D_IN / 4)];

    int t = threadIdx.x;          // output column 0..127
    int node0 = blockIdx.x * NODES_PER_BLOCK;

    #pragma unroll
    for (int r = 0; r < 2; r++) {
        int idx = t + r * D_OUT;           // 0..255
        int node = node0 + (idx >> 4);
        float4 v = make_float4(0.f, 0.f, 0.f, 0.f);
        if (node < n) {
            v = reinterpret_cast<const float4*>(g_rst)[(size_t)node * 16 + (idx & 15)];
        }
        s_rst4[idx] = v;
    }
    __syncthreads();

    float4 w[D_IN / 4];
    const float4* Wrow4 = reinterpret_cast<const float4*>(W + (size_t)t * D_IN);
    #pragma unroll
    for (int k = 0; k < D_IN / 4; k++) {
        w[k] = __ldg(&Wrow4[k]);
    }
    float bias = __ldg(&b[t]);

    #pragma unroll
    for (int i = 0; i < NODES_PER_BLOCK; i++) {
        int node = node0 + i;
        if (node >= n) break;
        float acc = bias;
        const float4* r4 = &s_rst4[i * (D_IN / 4)];
        #pragma unroll
        for (int k = 0; k < D_IN / 4; k++) {
            float4 v = r4[k];
            acc += v.x * w[k].x + v.y * w[k].y + v.z * w[k].z + v.w * w[k].w;
        }
        out[(size_t)node * D_OUT + t] = acc;
    }
}

// ---------------------------------------------------------------------------
// Inputs: feat [N*64] f32, radius [E] f32 (dead: weight = ones_like),
//         src [E] i32, dst [E] i32, W [128*64] f32, b [128] f32.
// Output: [N*128] f32.
// ---------------------------------------------------------------------------
extern "C" void kernel_launch(void* const* d_in, const int* in_sizes, int n_in,
                              void* d_out, int out_size) {
    const float* feat = (const float*)d_in[0];
    const int*   src  = (const int*)d_in[2];
    const int*   dst  = (const int*)d_in[3];
    const float* W    = (const float*)d_in[4];
    const float* b    = (const float*)d_in[5];
    float* out = (float*)d_out;

    int n = in_sizes[0] / D_IN;   // 100000
    int e = in_sizes[2];          // 1600000
    int nelem = n + 1;
    int nsb = (nelem + SCAN_CHUNK - 1) / SCAN_CHUNK;   // 25

    // CSR build: hist -> scan1 -> fill (bsum scanned in-block; g_cnt re-zeroed)
    hist_kernel<<<(e + 255) / 256, 256>>>(dst, e);
    scan1_kernel<<<nsb, 1024>>>(nelem);
    fill_kernel<<<(e + 255) / 256, 256>>>(src, dst, e, nelem, nsb);

    // Segment reduce: half-warp per node (launch #4 -> ncu window)
    {
        int blocks = (n * 16 + 255) / 256;
        accumulate_kernel<<<blocks, 256>>>(
            reinterpret_cast<const float4*>(feat), n, nsb);
    }

    // out = rst @ W^T + b
    gemm_out_kernel<<<(n + NODES_PER_BLOCK - 1) / NODES_PER_BLOCK, D_OUT>>>(
        W, b, out, n);
}

// round 13
// speedup vs baseline: 1.2044x; 1.1771x over previous
#include <cuda_runtime.h>
#include <stdint.h>

#define D_IN   64
#define D_OUT  128
#define MAX_NODES 100000
#define MAX_EDGES 1600000

#define SCAN_CHUNK 4096           // 1024 threads * 4 elems
#define SCAN_LOG2  12
#define SCAN_BLOCKS 32            // upper bound for smem scan (actual 25)

// Scratch (device globals; zero-initialized at module load; no allocs allowed)
__device__ int   g_cnt[MAX_NODES + 1];   // per-dst counts (zero at every entry)
__device__ int   g_off[MAX_NODES + 1];   // per-block exclusive offsets
__device__ int   g_rank[MAX_EDGES];      // within-bucket rank from histogram
__device__ int   g_esrc[MAX_EDGES];      // src ids sorted by dst bucket
__device__ int   g_bsum[SCAN_BLOCKS];    // RAW per-block aggregates
__device__ float g_rst[MAX_NODES * D_IN];

// ---------------------------------------------------------------------------
// 1) histogram of dst, 4 edges per thread (int4 index IO around the atomics).
//    atomicAdd return value = within-bucket rank. g_cnt zero at entry.
// ---------------------------------------------------------------------------
__global__ void hist_kernel(const int* __restrict__ dst, int e) {
    int i = blockIdx.x * blockDim.x + threadIdx.x;
    int base = i * 4;
    if (base + 3 < e) {
        int4 d = *reinterpret_cast<const int4*>(dst + base);
        int4 r;
        r.x = atomicAdd(&g_cnt[d.x], 1);
        r.y = atomicAdd(&g_cnt[d.y], 1);
        r.z = atomicAdd(&g_cnt[d.z], 1);
        r.w = atomicAdd(&g_cnt[d.w], 1);
        *reinterpret_cast<int4*>(g_rank + base) = r;
    } else {
        for (int k = base; k < e; k++) {
            g_rank[k] = atomicAdd(&g_cnt[dst[k]], 1);
        }
    }
}

// ---------------------------------------------------------------------------
// 2) per-block exclusive scan (1024 threads x 4 elems); writes per-block
//    offsets to g_off and RAW block aggregates to g_bsum.
// ---------------------------------------------------------------------------
__global__ __launch_bounds__(1024)
void scan1_kernel(int nelem) {
    __shared__ int s[1024];
    int t = threadIdx.x;
    int base = blockIdx.x * SCAN_CHUNK + t * 4;

    int v0 = (base + 0 < nelem) ? g_cnt[base + 0] : 0;
    int v1 = (base + 1 < nelem) ? g_cnt[base + 1] : 0;
    int v2 = (base + 2 < nelem) ? g_cnt[base + 2] : 0;
    int v3 = (base + 3 < nelem) ? g_cnt[base + 3] : 0;
    int tsum = v0 + v1 + v2 + v3;

    s[t] = tsum;
    __syncthreads();
    #pragma unroll
    for (int off = 1; off < 1024; off <<= 1) {
        int x = (t >= off) ? s[t - off] : 0;
        __syncthreads();
        if (t >= off) s[t] += x;
        __syncthreads();
    }
    int excl = s[t] - tsum;
    if (t == 1023) g_bsum[blockIdx.x] = s[1023];   // raw aggregate

    int run = excl;
    if (base + 0 < nelem) { g_off[base + 0] = run; } run += v0;
    if (base + 1 < nelem) { g_off[base + 1] = run; } run += v1;
    if (base + 2 < nelem) { g_off[base + 2] = run; } run += v2;
    if (base + 3 < nelem) { g_off[base + 3] = run; }
}

// Per-block smem preamble: exclusive scan of raw g_bsum aggregates (nsb<=32).
// Warp 0 only; all 32 lanes convergent; full mask. One barrier.
__device__ __forceinline__ void load_bsum_excl(int* s_bsumx, int nsb) {
    if (threadIdx.x < 32) {
        int lane = threadIdx.x;
        int v = (lane < nsb) ? __ldg(&g_bsum[lane]) : 0;
        int orig = v;
        #pragma unroll
        for (int off = 1; off < 32; off <<= 1) {
            int x = __shfl_up_sync(0xFFFFFFFFu, v, off);
            if (lane >= off) v += x;
        }
        s_bsumx[lane] = v - orig;
    }
    __syncthreads();
}

// ---------------------------------------------------------------------------
// 3) fill sorted src list, 2 edges per thread (int2 IO, 2 independent
//    scatter chains for MLP) + re-zero g_cnt for the next call.
// ---------------------------------------------------------------------------
__global__ __launch_bounds__(256)
void fill_kernel(const int* __restrict__ src,
                 const int* __restrict__ dst, int e, int nelem, int nsb) {
    __shared__ int s_bsumx[SCAN_BLOCKS];
    load_bsum_excl(s_bsumx, nsb);

    int i = blockIdx.x * blockDim.x + threadIdx.x;
    int base = i * 2;
    if (base + 1 < e) {
        int2 d = *reinterpret_cast<const int2*>(dst + base);
        int2 r = *reinterpret_cast<const int2*>(g_rank + base);
        int2 sc = *reinterpret_cast<const int2*>(src + base);
        int p0 = __ldg(&g_off[d.x]) + s_bsumx[d.x >> SCAN_LOG2] + r.x;
        int p1 = __ldg(&g_off[d.y]) + s_bsumx[d.y >> SCAN_LOG2] + r.y;
        g_esrc[p0] = sc.x;
        g_esrc[p1] = sc.y;
    } else if (base < e) {
        int d = dst[base];
        int p = __ldg(&g_off[d]) + s_bsumx[d >> SCAN_LOG2] + g_rank[base];
        g_esrc[p] = src[base];
    }
    if (i < nelem) g_cnt[i] = 0;
}

// ---------------------------------------------------------------------------
// 4) segment reduce: HALF-WARP (16 lanes x float4) per node, warp covers 2
//    nodes. 4-deep unroll, two accumulator chains (R8/R12-measured: 38.3us).
// ---------------------------------------------------------------------------
__global__ __launch_bounds__(256)
void accumulate_kernel(const float4* __restrict__ feat4, int n, int nsb) {
    __shared__ int s_bsumx[SCAN_BLOCKS];
    load_bsum_excl(s_bsumx, nsb);

    int gtid = blockIdx.x * blockDim.x + threadIdx.x;
    int node = gtid >> 4;          // 16 lanes per node
    int hl   = threadIdx.x & 15;   // float4 index within the 64-float row
    if (node >= n) return;

    float4 acc0 = __ldg(&feat4[(size_t)node * 16 + hl]);
    float4 acc1 = make_float4(0.f, 0.f, 0.f, 0.f);

    int j   = __ldg(&g_off[node])     + s_bsumx[node >> SCAN_LOG2];
    int end = __ldg(&g_off[node + 1]) + s_bsumx[(node + 1) >> SCAN_LOG2];

    for (; j + 4 <= end; j += 4) {
        int s0 = __ldg(&g_esrc[j + 0]);
        int s1 = __ldg(&g_esrc[j + 1]);
        int s2 = __ldg(&g_esrc[j + 2]);
        int s3 = __ldg(&g_esrc[j + 3]);
        float4 v0 = __ldg(&feat4[(size_t)s0 * 16 + hl]);
        float4 v1 = __ldg(&feat4[(size_t)s1 * 16 + hl]);
        float4 v2 = __ldg(&feat4[(size_t)s2 * 16 + hl]);
        float4 v3 = __ldg(&feat4[(size_t)s3 * 16 + hl]);
        acc0.x += v0.x + v1.x;  acc1.x += v2.x + v3.x;
        acc0.y += v0.y + v1.y;  acc1.y += v2.y + v3.y;
        acc0.z += v0.z + v1.z;  acc1.z += v2.z + v3.z;
        acc0.w += v0.w + v1.w;  acc1.w += v2.w + v3.w;
    }
    for (; j < end; j++) {
        int s = __ldg(&g_esrc[j]);
        float4 v = __ldg(&feat4[(size_t)s * 16 + hl]);
        acc0.x += v.x; acc0.y += v.y; acc0.z += v.z; acc0.w += v.w;
    }

    float4 outv = make_float4(acc0.x + acc1.x, acc0.y + acc1.y,
                              acc0.z + acc1.z, acc0.w + acc1.w);
    reinterpret_cast<float4*>(g_rst)[(size_t)node * 16 + hl] = outv;
}

// ---------------------------------------------------------------------------
// 5) out[n][o] = b[o] + sum_d rst[n][d] * W[o][d]
//    64 nodes per block (4x better W-load amortization: 200MB -> 50MB L2),
//    two FFMA chains per node for ILP.
// ---------------------------------------------------------------------------
#define NODES_PER_BLOCK 64

__global__ __launch_bounds__(D_OUT, 4)
void gemm_out_kernel(const float* __restrict__ W,
                     const float* __restrict__ b,
                     float* __restrict__ out,
                     int n) {
    __shared__ float4 s_rst4[NODES_PER_BLOCK * (D_IN / 4)];   // 16 KB

    int t = threadIdx.x;          // output column 0..127
    int node0 = blockIdx.x * NODES_PER_BLOCK;

    // Stage 64 rst rows: 1024 float4 -> 8 per thread.
    #pragma unroll
    for (int r = 0; r < 8; r++) {
        int idx = t + r * D_OUT;           // 0..1023
        int node = node0 + (idx >> 4);
        float4 v = make_float4(0.f, 0.f, 0.f, 0.f);
        if (node < n) {
            v = reinterpret_cast<const float4*>(g_rst)[(size_t)node * 16 + (idx & 15)];
        }
        s_rst4[idx] = v;
    }
    __syncthreads();

    float4 w[D_IN / 4];
    const float4* Wrow4 = reinterpret_cast<const float4*>(W + (size_t)t * D_IN);
    #pragma unroll
    for (int k = 0; k < D_IN / 4; k++) {
        w[k] = __ldg(&Wrow4[k]);
    }
    float bias = __ldg(&b[t]);

    #pragma unroll 4
    for (int i = 0; i < NODES_PER_BLOCK; i++) {
        int node = node0 + i;
        if (node >= n) break;
        float acc0 = bias;
        float acc1 = 0.f;
        const float4* r4 = &s_rst4[i * (D_IN / 4)];
        #pragma unroll
        for (int k = 0; k < 8; k++) {
            float4 va = r4[k];
            float4 vb = r4[k + 8];
            acc0 += va.x * w[k].x + va.y * w[k].y + va.z * w[k].z + va.w * w[k].w;
            acc1 += vb.x * w[k + 8].x + vb.y * w[k + 8].y
                  + vb.z * w[k + 8].z + vb.w * w[k + 8].w;
        }
        out[(size_t)node * D_OUT + t] = acc0 + acc1;
    }
}

// ---------------------------------------------------------------------------
// Inputs: feat [N*64] f32, radius [E] f32 (dead: weight = ones_like),
//         src [E] i32, dst [E] i32, W [128*64] f32, b [128] f32.
// Output: [N*128] f32.
// ---------------------------------------------------------------------------
extern "C" void kernel_launch(void* const* d_in, const int* in_sizes, int n_in,
                              void* d_out, int out_size) {
    const float* feat = (const float*)d_in[0];
    const int*   src  = (const int*)d_in[2];
    const int*   dst  = (const int*)d_in[3];
    const float* W    = (const float*)d_in[4];
    const float* b    = (const float*)d_in[5];
    float* out = (float*)d_out;

    int n = in_sizes[0] / D_IN;   // 100000
    int e = in_sizes[2];          // 1600000
    int nelem = n + 1;
    int nsb = (nelem + SCAN_CHUNK - 1) / SCAN_CHUNK;   // 25

    // CSR build: hist (4 edges/thr) -> scan1 -> fill (2 edges/thr)
    {
        int threads4 = (e + 3) / 4;
        hist_kernel<<<(threads4 + 255) / 256, 256>>>(dst, e);
    }
    scan1_kernel<<<nsb, 1024>>>(nelem);
    {
        int threads2 = (e + 1) / 2;
        fill_kernel<<<(threads2 + 255) / 256, 256>>>(src, dst, e, nelem, nsb);
    }

    // Segment reduce: half-warp per node (launch #4 -> ncu window)
    {
        int blocks = (n * 16 + 255) / 256;
        accumulate_kernel<<<blocks, 256>>>(
            reinterpret_cast<const float4*>(feat), n, nsb);
    }

    // out = rst @ W^T + b   (64 nodes per block)
    gemm_out_kernel<<<(n + NODES_PER_BLOCK - 1) / NODES_PER_BLOCK, D_OUT>>>(
        W, b, out, n);
}